// round 1
// baseline (speedup 1.0000x reference)
#include <cuda_runtime.h>
#include <cstdint>

// PointPillarsScatter:
//   out[b, c, x, y] = voxel_features[n, c]  where coords[n] = (b, 0, y, x), else 0
// Output layout: ((b*64 + c)*512 + x)*512 + y, fp32, 4*64*512*512 = 67,108,864 elems.
//
// Strategy: inverse gather.
//   1) clear a device-resident (b,x,y) -> pillar+1 map (4 MB)
//   2) fill the map from coords (120k cheap writes)
//   3) one coalesced pass over the output: each thread owns 4 consecutive y,
//      loops the 64 channels, predicated-gathers from the feature table
//      (30.7 MB, L2-resident) and issues streaming float4 stores so the
//      256 MB output never thrashes L2.

#define BATCH 4
#define NCH   64
#define NX    512
#define NY    512
#define NPIX  (BATCH * NX * NY)

__device__ int g_map[NPIX];  // stores pillar_index + 1; 0 = empty

__global__ void zero_map_kernel() {
    int i = blockIdx.x * blockDim.x + threadIdx.x;  // over int4 quads
    reinterpret_cast<int4*>(g_map)[i] = make_int4(0, 0, 0, 0);
}

__global__ void fill_map_kernel(const int* __restrict__ coords, int n) {
    int i = blockIdx.x * blockDim.x + threadIdx.x;
    if (i < n) {
        int b = coords[4 * i + 0];
        int y = coords[4 * i + 2];
        int x = coords[4 * i + 3];
        g_map[(b * NX + x) * NY + y] = i + 1;
    }
}

// Grid: BATCH*NX blocks (one per (b,x) row), 128 threads (4 y's per thread).
__global__ void __launch_bounds__(128) gather_kernel(
    const float* __restrict__ feat, float* __restrict__ out) {
    const int bx = blockIdx.x;          // b*NX + x
    const int b  = bx >> 9;             // NX = 512
    const int x  = bx & (NX - 1);
    const int y0 = threadIdx.x << 2;    // 4 consecutive y per thread

    // One aligned int4 map read per thread; kept in registers across channels.
    const int4 m = *reinterpret_cast<const int4*>(&g_map[bx * NY + y0]);
    const int n0 = m.x - 1, n1 = m.y - 1, n2 = m.z - 1, n3 = m.w - 1;

    const float* f0 = feat + (long long)n0 * NCH;
    const float* f1 = feat + (long long)n1 * NCH;
    const float* f2 = feat + (long long)n2 * NCH;
    const float* f3 = feat + (long long)n3 * NCH;

    // out offset for c=0 at this (b, x, y0); +NX*NY per channel
    size_t base = (size_t)b * NCH * NX * NY + (size_t)x * NY + (size_t)y0;

#pragma unroll 8
    for (int c = 0; c < NCH; c++) {
        float4 v;
        v.x = (n0 >= 0) ? __ldg(f0 + c) : 0.0f;
        v.y = (n1 >= 0) ? __ldg(f1 + c) : 0.0f;
        v.z = (n2 >= 0) ? __ldg(f2 + c) : 0.0f;
        v.w = (n3 >= 0) ? __ldg(f3 + c) : 0.0f;
        __stcs(reinterpret_cast<float4*>(out + base + (size_t)c * (NX * NY)), v);
    }
}

extern "C" void kernel_launch(void* const* d_in, const int* in_sizes, int n_in,
                              void* d_out, int out_size) {
    const float* feat   = (const float*)d_in[0];
    const int*   coords = (const int*)d_in[1];
    float*       out    = (float*)d_out;

    const int n = in_sizes[0] / NCH;  // number of pillars

    // 1) clear map: NPIX/4 int4 stores
    zero_map_kernel<<<(NPIX / 4) / 256, 256>>>();
    // 2) fill map from coords
    fill_map_kernel<<<(n + 255) / 256, 256>>>(coords, n);
    // 3) coalesced gather into output
    gather_kernel<<<BATCH * NX, 128>>>(feat, out);
}

// round 2
// speedup vs baseline: 1.0792x; 1.0792x over previous
#include <cuda_runtime.h>
#include <cstdint>

// PointPillarsScatter:
//   out[b, c, x, y] = voxel_features[n, c]  where coords[n] = (b, 0, y, x), else 0
// Output layout: ((b*64 + c)*512 + x)*512 + y, fp32, 4*64*512*512 = 67,108,864 elems.
//
// Strategy: inverse gather, 2 kernels.
//   1) fill a device-resident (b,x,y) -> pillar+1 map (120k cheap writes; map is
//      guaranteed all-zero at entry: zero-initialized at module load, and the
//      gather kernel re-zeroes every quad it reads, restoring the invariant).
//   2) one coalesced pass over the output: each thread owns 4 consecutive y,
//      loops channels 4 at a time with float4 gathers from the feature table
//      (30.7 MB, L2-resident), 4x4 register transpose, streaming float4 stores
//      so the 256 MB output never thrashes L2.

#define BATCH 4
#define NCH   64
#define NX    512
#define NY    512
#define NPIX  (BATCH * NX * NY)

__device__ int g_map[NPIX];  // stores pillar_index + 1; 0 = empty. All-zero between launches.

__global__ void fill_map_kernel(const int* __restrict__ coords, int n) {
    int i = blockIdx.x * blockDim.x + threadIdx.x;
    if (i < n) {
        int b = coords[4 * i + 0];
        int y = coords[4 * i + 2];
        int x = coords[4 * i + 3];
        g_map[(b * NX + x) * NY + y] = i + 1;
    }
}

// Grid: BATCH*NX blocks (one per (b,x) row), 128 threads (4 consecutive y per thread).
__global__ void __launch_bounds__(128) gather_kernel(
    const float* __restrict__ feat, float* __restrict__ out) {
    const int bx = blockIdx.x;          // b*NX + x
    const int b  = bx >> 9;             // NX = 512
    const int x  = bx & (NX - 1);
    const int y0 = threadIdx.x << 2;

    // One aligned int4 map read per thread, then restore the all-zero invariant.
    int4* mp = reinterpret_cast<int4*>(&g_map[bx * NY + y0]);
    const int4 m = *mp;
    *mp = make_int4(0, 0, 0, 0);

    const int n0 = m.x - 1, n1 = m.y - 1, n2 = m.z - 1, n3 = m.w - 1;

    // Per-pillar feature rows as float4 (16 x float4 = 64 channels), 16B aligned.
    const float4* f0 = reinterpret_cast<const float4*>(feat + (size_t)n0 * NCH);
    const float4* f1 = reinterpret_cast<const float4*>(feat + (size_t)n1 * NCH);
    const float4* f2 = reinterpret_cast<const float4*>(feat + (size_t)n2 * NCH);
    const float4* f3 = reinterpret_cast<const float4*>(feat + (size_t)n3 * NCH);

    // out offset for c=0 at this (b, x, y0); +NX*NY per channel
    const size_t base = (size_t)b * NCH * NX * NY + (size_t)x * NY + (size_t)y0;
    const float4 zero = make_float4(0.f, 0.f, 0.f, 0.f);

#pragma unroll
    for (int cg = 0; cg < NCH / 4; cg++) {
        const float4 g0 = (n0 >= 0) ? __ldg(f0 + cg) : zero;
        const float4 g1 = (n1 >= 0) ? __ldg(f1 + cg) : zero;
        const float4 g2 = (n2 >= 0) ? __ldg(f2 + cg) : zero;
        const float4 g3 = (n3 >= 0) ? __ldg(f3 + cg) : zero;

        // 4x4 register transpose: channel-major -> y-major
        const float4 o0 = make_float4(g0.x, g1.x, g2.x, g3.x);
        const float4 o1 = make_float4(g0.y, g1.y, g2.y, g3.y);
        const float4 o2 = make_float4(g0.z, g1.z, g2.z, g3.z);
        const float4 o3 = make_float4(g0.w, g1.w, g2.w, g3.w);

        float* p = out + base + (size_t)(4 * cg) * (NX * NY);
        __stcs(reinterpret_cast<float4*>(p),                     o0);
        __stcs(reinterpret_cast<float4*>(p + 1 * NX * NY),       o1);
        __stcs(reinterpret_cast<float4*>(p + 2 * NX * NY),       o2);
        __stcs(reinterpret_cast<float4*>(p + 3 * NX * NY),       o3);
    }
}

extern "C" void kernel_launch(void* const* d_in, const int* in_sizes, int n_in,
                              void* d_out, int out_size) {
    const float* feat   = (const float*)d_in[0];
    const int*   coords = (const int*)d_in[1];
    float*       out    = (float*)d_out;

    const int n = in_sizes[0] / NCH;  // number of pillars

    fill_map_kernel<<<(n + 255) / 256, 256>>>(coords, n);
    gather_kernel<<<BATCH * NX, 128>>>(feat, out);
}